// round 1
// baseline (speedup 1.0000x reference)
#include <cuda_runtime.h>
#include <cstdint>

#define NLV 16
#define TSIZE (1u << 19)
#define HMASK (TSIZE - 1u)
#define PRIME1 2654435761u
#define PRIME2 805459861u

static __device__ __forceinline__ float2 lerp2(float2 a, float2 b, float w) {
    float u = 1.0f - w;
    return make_float2(a.x * u + b.x * w, a.y * u + b.y * w);
}

__global__ void __launch_bounds__(256)
hashenc_kernel(const float* __restrict__ x,
               const float2* __restrict__ emb,   // [16][2^19] float2
               const float* __restrict__ lw,     // [16]
               const float* __restrict__ bmin,   // [3]
               const float* __restrict__ bmax,   // [3]
               float* __restrict__ out,          // [N, 32]
               int n)
{
    // floor(16 * b^i), b = exp((ln512 - ln16)/15) evaluated in float32 (numpy chain)
    const float RES[NLV] = {16.f, 20.f, 25.f, 32.f, 40.f, 50.f, 64.f, 80.f,
                            101.f, 128.f, 161.f, 203.f, 256.f, 322.f, 406.f, 512.f};

    int tid = blockIdx.x * blockDim.x + threadIdx.x;
    if (tid >= n) return;

    float x0 = x[3 * (size_t)tid + 0];
    float x1 = x[3 * (size_t)tid + 1];
    float x2 = x[3 * (size_t)tid + 2];

    float bm0 = __ldg(&bmin[0]), bm1 = __ldg(&bmin[1]), bm2 = __ldg(&bmin[2]);
    float bM0 = __ldg(&bmax[0]), bM1 = __ldg(&bmax[1]), bM2 = __ldg(&bmax[2]);

    float xc0 = fminf(fmaxf(x0, bm0), bM0);
    float xc1 = fminf(fmaxf(x1, bm1), bM1);
    float xc2 = fminf(fmaxf(x2, bm2), bM2);

    float o[2 * NLV];

#pragma unroll
    for (int l = 0; l < NLV; l++) {
        float res = RES[l];
        // grid = (box_max - box_min) / res  (per component)
        float g0 = (bM0 - bm0) / res;
        float g1 = (bM1 - bm1) / res;
        float g2 = (bM2 - bm2) / res;
        // bottom-left cell: floor((xc - box_min) / grid)
        float f0 = floorf((xc0 - bm0) / g0);
        float f1 = floorf((xc1 - bm1) / g1);
        float f2 = floorf((xc2 - bm2) / g2);
        // vmin / vmax, weights use raw x (matches reference)
        float v0 = f0 * g0 + bm0;
        float v1 = f1 * g1 + bm1;
        float v2 = f2 * g2 + bm2;
        float wx = (x0 - v0) / ((v0 + g0) - v0);
        float wy = (x1 - v1) / ((v1 + g1) - v1);
        float wz = (x2 - v2) / ((v2 + g2) - v2);

        unsigned b0 = (unsigned)(int)f0;
        unsigned b1 = (unsigned)(int)f1;
        unsigned b2 = (unsigned)(int)f2;

        unsigned hx0 = b0;                      // * PRIME0 (=1)
        unsigned hx1 = b0 + 1u;
        unsigned hy0 = b1 * PRIME1;
        unsigned hy1 = (b1 + 1u) * PRIME1;
        unsigned hz0 = b2 * PRIME2;
        unsigned hz1 = (b2 + 1u) * PRIME2;

        const float2* t = emb + (size_t)l * TSIZE;

        // corner index c = i*4 + j*2 + k
        float2 e000 = __ldg(&t[(hx0 ^ hy0 ^ hz0) & HMASK]);
        float2 e001 = __ldg(&t[(hx0 ^ hy0 ^ hz1) & HMASK]);
        float2 e010 = __ldg(&t[(hx0 ^ hy1 ^ hz0) & HMASK]);
        float2 e011 = __ldg(&t[(hx0 ^ hy1 ^ hz1) & HMASK]);
        float2 e100 = __ldg(&t[(hx1 ^ hy0 ^ hz0) & HMASK]);
        float2 e101 = __ldg(&t[(hx1 ^ hy0 ^ hz1) & HMASK]);
        float2 e110 = __ldg(&t[(hx1 ^ hy1 ^ hz0) & HMASK]);
        float2 e111 = __ldg(&t[(hx1 ^ hy1 ^ hz1) & HMASK]);

        // trilinear: blend x, then y, then z (exact reference op order)
        float2 cx0 = lerp2(e000, e100, wx);
        float2 cx1 = lerp2(e001, e101, wx);
        float2 cx2 = lerp2(e010, e110, wx);
        float2 cx3 = lerp2(e011, e111, wx);
        float2 c0 = lerp2(cx0, cx2, wy);
        float2 c1 = lerp2(cx1, cx3, wy);
        float2 c  = lerp2(c0, c1, wz);

        float gate = 1.0f / (1.0f + expf(-__ldg(&lw[l])));
        o[2 * l + 0] = c.x * gate;
        o[2 * l + 1] = c.y * gate;
    }

    float4* o4 = reinterpret_cast<float4*>(out + (size_t)tid * (2 * NLV));
#pragma unroll
    for (int q = 0; q < 8; q++)
        o4[q] = make_float4(o[4 * q + 0], o[4 * q + 1], o[4 * q + 2], o[4 * q + 3]);
}

extern "C" void kernel_launch(void* const* d_in, const int* in_sizes, int n_in,
                              void* d_out, int out_size) {
    const float*  x    = (const float*)d_in[0];
    const float2* emb  = (const float2*)d_in[1];
    const float*  lw   = (const float*)d_in[2];
    const float*  bmin = (const float*)d_in[3];
    const float*  bmax = (const float*)d_in[4];
    float* out = (float*)d_out;

    int n = in_sizes[0] / 3;
    int blocks = (n + 255) / 256;
    hashenc_kernel<<<blocks, 256>>>(x, emb, lw, bmin, bmax, out, n);
}